// round 15
// baseline (speedup 1.0000x reference)
#include <cuda_runtime.h>
#include <cstddef>

#define HH 51
#define NT 416        // 13 warps: gate = warp*4+ju per cls, k split across half-warps
#define BT 16
#define TT 512
#define BB 2048
#define TCH 64
#define KQ 26         // k-rows per half (second half covers k 26..51, k51 = zero pad)

// shared buffer layout (floats). 53 rows per h buffer: 26 + 1 pad row + 26.
#define HBUF  848     // 53*16
#define H2OFF 1712    // 2*848 + 16 (64B skew vs h1 -> conflict-free dual-array STS)
#define XSOFF 3408
#define FCWOFF 4432
#define SMF 4496

typedef unsigned long long u64;

__device__ __forceinline__ u64 pack2(float lo, float hi) {
    u64 r; asm("mov.b64 %0, {%1,%2};" : "=l"(r) : "f"(lo), "f"(hi)); return r;
}
__device__ __forceinline__ void unpack2(u64 v, float& lo, float& hi) {
    asm("mov.b64 {%0,%1}, %2;" : "=f"(lo), "=f"(hi) : "l"(v));
}
__device__ __forceinline__ u64 fma2(u64 a, u64 b, u64 c) {
    u64 d; asm("fma.rn.f32x2 %0, %1, %2, %3;" : "=l"(d) : "l"(a), "l"(b), "l"(c)); return d;
}
__device__ __forceinline__ u64 add2(u64 a, u64 b) {
    u64 d; asm("add.rn.f32x2 %0, %1, %2;" : "=l"(d) : "l"(a), "l"(b)); return d;
}
// v PRE-SCALED by log2 const (weights folded). act = a*rcp(1+ex2(v)) + d
__device__ __forceinline__ float actf2(float v, float a, float d) {
    float e; asm("ex2.approx.ftz.f32 %0, %1;" : "=f"(e) : "f"(v));
    float r; asm("rcp.approx.ftz.f32 %0, %1;" : "=f"(r) : "f"(1.f + e));
    return fmaf(a, r, d);
}
#define C_SIG (-1.442695041f)
#define C_TNH ( 2.885390082f)
__device__ __forceinline__ float tanh_c(float v) {
    float e; asm("ex2.approx.ftz.f32 %0, %1;" : "=f"(e) : "f"(v * C_TNH));
    float r; asm("rcp.approx.ftz.f32 %0, %1;" : "=f"(r) : "f"(1.f + e));
    return fmaf(-2.f, r, 1.f);
}

// Transpose gate x batch among the 16-lane half (cls = lane bits 2..3 -> xor4, xor8),
// update cell state in regs, write h row. acc[i] = preacts for batches (2i,2i+1).
__device__ __forceinline__ void gates_update(
    u64 acc[8], float a0, float d0,
    int bit0, int bit1, float (&cst)[4],
    float* __restrict__ hw, int rowj, bool commit)
{
    float s[16];
#pragma unroll
    for (int i = 0; i < 8; ++i) unpack2(acc[i], s[2*i], s[2*i+1]);
#pragma unroll
    for (int i = 0; i < 16; ++i) s[i] = actf2(s[i], a0, d0);

    // round 1 (xor 4): exchange quarters q with q&1 != bit0
    float a1[8];
    {
        const int qx0 = bit0 ? 0 : 1, qx1 = bit0 ? 2 : 3;
        const int qk0 = bit0 ? 1 : 0, qk1 = bit0 ? 3 : 2;
        float ex[8];
#pragma unroll
        for (int i = 0; i < 4; ++i) { ex[i] = s[qx0*4+i]; ex[4+i] = s[qx1*4+i]; }
#pragma unroll
        for (int i = 0; i < 8; ++i) a1[i] = __shfl_xor_sync(0xFFFFFFFFu, ex[i], 4);
        float k0[8];
#pragma unroll
        for (int i = 0; i < 4; ++i) { k0[i] = s[qk0*4+i]; k0[4+i] = s[qk1*4+i]; }
#pragma unroll
        for (int i = 0; i < 8; ++i) s[i] = k0[i];
    }
    // round 2 (xor 8): keep quarter with q>>1 == bit1
    float r0[4], r1[4];
    {
        float ex[8];
#pragma unroll
        for (int i = 0; i < 4; ++i) {
            ex[i]   = bit1 ? s[i]  : s[4+i];
            ex[4+i] = bit1 ? a1[i] : a1[4+i];
        }
#pragma unroll
        for (int i = 0; i < 8; ++i) ex[i] = __shfl_xor_sync(0xFFFFFFFFu, ex[i], 8);
#pragma unroll
        for (int i = 0; i < 4; ++i) {
            r0[i] = ex[i]; r1[i] = ex[4+i];
            s[i]  = bit1 ? s[4+i]  : s[i];
            a1[i] = bit1 ? a1[4+i] : a1[i];
        }
    }
    float4 hv;
    float* hp = &hv.x;
#pragma unroll
    for (int i = 0; i < 4; ++i) {
        float iv = bit1 ? (bit0 ? r1[i] : r0[i]) : (bit0 ? a1[i] : s[i]);
        float fv = bit1 ? (bit0 ? r0[i] : r1[i]) : (bit0 ? s[i]  : a1[i]);
        float gv = bit1 ? (bit0 ? a1[i] : s[i])  : (bit0 ? r1[i] : r0[i]);
        float ov = bit1 ? (bit0 ? s[i]  : a1[i]) : (bit0 ? r0[i] : r1[i]);
        float c = fv * cst[i] + iv * gv;
        if (commit) cst[i] = c;
        hp[i] = ov * tanh_c(c);
    }
    if (commit) *(float4*)&hw[(rowj << 4) + (bit1*2 + bit0)*4] = hv;
}

__global__ void __launch_bounds__(NT, 1) lstm2_ksplit1b_kernel(
    const float* __restrict__ x,
    const float* __restrict__ Wih1, const float* __restrict__ bih1,
    const float* __restrict__ Whh1, const float* __restrict__ bhh1,
    const float* __restrict__ Wih2, const float* __restrict__ bih2,
    const float* __restrict__ Whh2, const float* __restrict__ bhh2,
    const float* __restrict__ fcwg, const float* __restrict__ fcbg,
    float* __restrict__ out)
{
    __shared__ __align__(16) float buf[SMF];

    const int tid  = threadIdx.x;
    const int b0   = blockIdx.x * BT;
    const int lane = tid & 31, warp = tid >> 5;
    const int s    = lane >> 4;                  // k-half
    const int q    = lane & 15;
    const int cls  = q >> 2;                     // 0:i 1:f 2:g 3:o
    const int ju   = q & 3;
    const int j    = warp * 4 + ju;              // 0..51 (51 pad)
    const bool jv  = (j < HH);
    const int gs   = cls*HH + (jv ? j : HH - 1);
    const int bit0 = cls & 1, bit1 = cls >> 1;
    const int koff = s * KQ;
    const int rowj = j + (j >= KQ);              // skip pad row 26

    const float sc = (cls == 2) ? C_TNH : C_SIG;
    const float a0 = (cls == 2) ? -2.f  : 1.f;
    const float d0 = (cls == 2) ?  1.f  : 0.f;

    // ---- weights (pre-scaled) into regs; k-half only; kg=51 -> 0 ----
    float W1r[KQ], Wi2r[KQ], Wh2r[KQ];
#pragma unroll
    for (int kk = 0; kk < KQ; ++kk) {
        int kg = koff + kk;
        bool kvv = (kg < HH);
        W1r[kk]  = kvv ? sc * Whh1[gs*HH + kg] : 0.f;
        Wi2r[kk] = kvv ? sc * Wih2[gs*HH + kg] : 0.f;
        Wh2r[kk] = kvv ? sc * Whh2[gs*HH + kg] : 0.f;
    }
    // bias/x-term only on s=0 half (s=1 contributes pure k-partials)
    const float b1v = s ? 0.f : sc * (bih1[gs] + bhh1[gs]);
    const float b2v = s ? 0.f : sc * (bih2[gs] + bhh2[gs]);
    const float wxv = s ? 0.f : sc * Wih1[gs];
    const u64 b1d  = pack2(b1v, b1v);
    const u64 b2d  = pack2(b2v, b2v);
    const u64 wi1d = pack2(wxv, wxv);

    for (int i = tid; i < SMF; i += NT) buf[i] = 0.f;
    __syncthreads();
    if (tid < HH) buf[FCWOFF + tid] = fcwg[tid];
    const float fcb = fcbg[0];

    float cst[4] = {0.f, 0.f, 0.f, 0.f};   // s=0: cell-2 state; s=1: cell-1 state
    const int hof = s ? 27*16 : 0;          // my k-half row base (row 27 = k 26)

    // ---- stage x chunk 0 ----
    for (int i = tid; i < BT*TCH; i += NT) {
        int b = i >> 6, u = i & 63;
        buf[XSOFF + (u << 4) + b] = x[(size_t)(b0 + b) * TT + u];
    }
    __syncthreads();

    // ---- prologue: cell1(0) = act(b1 + wi1*x(0)); s=1 commits it ----
    {
        u64 a1c[8], keep[8];
        const ulonglong2* xr = (const ulonglong2*)&buf[XSOFF];
        ulonglong2 x01 = xr[0], x23 = xr[1], x45 = xr[2], x67 = xr[3];
        a1c[0] = fma2(wi1d, x01.x, b1d);
        a1c[1] = fma2(wi1d, x01.y, b1d);
        a1c[2] = fma2(wi1d, x23.x, b1d);
        a1c[3] = fma2(wi1d, x23.y, b1d);
        a1c[4] = fma2(wi1d, x45.x, b1d);
        a1c[5] = fma2(wi1d, x45.y, b1d);
        a1c[6] = fma2(wi1d, x67.x, b1d);
        a1c[7] = fma2(wi1d, x67.y, b1d);
#pragma unroll
        for (int i = 0; i < 8; ++i) {
            u64 sv = s ? 0ull : a1c[i];
            keep[i] = __shfl_xor_sync(0xFFFFFFFFu, sv, 16);   // s=1 gets a1c, s=0 gets 0
        }
        gates_update(keep, a0, d0, bit0, bit1, cst, buf /*h1 ping*/, rowj, jv && (s == 1));
    }
    __syncthreads();

    // ========== main loop: one barrier per timestep ==========
    // invariant: h1(t) in h1buf[t&1], h2(t-1) in h2buf[(t+1)&1]
    for (int t = 0; t < TT; ++t) {
        // fc head for t-1 (h2buf[(t-1)&1] is stable this iteration)
        if (t > 0 && tid < 128) {
            const float* h2o = buf + H2OFF + ((t - 1) & 1) * HBUF;
            int b = tid >> 3, qq = tid & 7;
            float a = 0.f;
            for (int k = qq; k < HH; k += 8) {
                int rk = k + (k >= KQ);
                a += h2o[(rk << 4) + b] * buf[FCWOFF + k];
            }
            a += __shfl_xor_sync(0xFFFFFFFFu, a, 1);
            a += __shfl_xor_sync(0xFFFFFFFFu, a, 2);
            a += __shfl_xor_sync(0xFFFFFFFFu, a, 4);
            if (qq == 0) out[(size_t)(b0 + b) * TT + (t - 1)] = a + fcb;
        }

        const int tn = t + 1;
        if ((tn & 63) == 0 && t < TT - 1) {
            __syncthreads();
            for (int i = tid; i < BT*TCH; i += NT) {
                int b = i >> 6, u = i & 63;
                buf[XSOFF + (u << 4) + b] = x[(size_t)(b0 + b) * TT + tn + u];
            }
            __syncthreads();
        }
        const int tc = tn & 63;   // t=511: stale but discarded

        float* h1c = buf + (t & 1) * HBUF;
        float* h1n = buf + ((t + 1) & 1) * HBUF;
        float* h2p = buf + H2OFF + ((t + 1) & 1) * HBUF;
        float* h2c = buf + H2OFF + (t & 1) * HBUF;
        const float* h1base = h1c + hof;
        const float* h2base = h2p + hof;

        // ---- unified gate phase, k-half partials ----
        u64 a1c[8], a2c[8];
        {
            const ulonglong2* xr = (const ulonglong2*)&buf[XSOFF + (tc << 4)];
            ulonglong2 x01 = xr[0], x23 = xr[1], x45 = xr[2], x67 = xr[3];
            a1c[0] = fma2(wi1d, x01.x, b1d);
            a1c[1] = fma2(wi1d, x01.y, b1d);
            a1c[2] = fma2(wi1d, x23.x, b1d);
            a1c[3] = fma2(wi1d, x23.y, b1d);
            a1c[4] = fma2(wi1d, x45.x, b1d);
            a1c[5] = fma2(wi1d, x45.y, b1d);
            a1c[6] = fma2(wi1d, x67.x, b1d);
            a1c[7] = fma2(wi1d, x67.y, b1d);
        }
#pragma unroll
        for (int i = 0; i < 8; ++i) a2c[i] = b2d;

#pragma unroll
        for (int kk = 0; kk < KQ; ++kk) {
            u64 w1 = pack2(W1r[kk],  W1r[kk]);
            u64 wi = pack2(Wi2r[kk], Wi2r[kk]);
            u64 wh = pack2(Wh2r[kk], Wh2r[kk]);
            const ulonglong2* hp = (const ulonglong2*)&h1base[kk << 4];
            const ulonglong2* hq = (const ulonglong2*)&h2base[kk << 4];
            ulonglong2 p0 = hp[0], p1 = hp[1], p2 = hp[2], p3 = hp[3];
            ulonglong2 q0 = hq[0], q1 = hq[1], q2 = hq[2], q3 = hq[3];
            a1c[0] = fma2(w1, p0.x, a1c[0]);
            a1c[1] = fma2(w1, p0.y, a1c[1]);
            a1c[2] = fma2(w1, p1.x, a1c[2]);
            a1c[3] = fma2(w1, p1.y, a1c[3]);
            a1c[4] = fma2(w1, p2.x, a1c[4]);
            a1c[5] = fma2(w1, p2.y, a1c[5]);
            a1c[6] = fma2(w1, p3.x, a1c[6]);
            a1c[7] = fma2(w1, p3.y, a1c[7]);
            a2c[0] = fma2(wi, p0.x, a2c[0]);
            a2c[1] = fma2(wi, p0.y, a2c[1]);
            a2c[2] = fma2(wi, p1.x, a2c[2]);
            a2c[3] = fma2(wi, p1.y, a2c[3]);
            a2c[4] = fma2(wi, p2.x, a2c[4]);
            a2c[5] = fma2(wi, p2.y, a2c[5]);
            a2c[6] = fma2(wi, p3.x, a2c[6]);
            a2c[7] = fma2(wi, p3.y, a2c[7]);
            a2c[0] = fma2(wh, q0.x, a2c[0]);
            a2c[1] = fma2(wh, q0.y, a2c[1]);
            a2c[2] = fma2(wh, q1.x, a2c[2]);
            a2c[3] = fma2(wh, q1.y, a2c[3]);
            a2c[4] = fma2(wh, q2.x, a2c[4]);
            a2c[5] = fma2(wh, q2.y, a2c[5]);
            a2c[6] = fma2(wh, q3.x, a2c[6]);
            a2c[7] = fma2(wh, q3.y, a2c[7]);
        }

        // ---- cross-half reduction: s=0 keeps a2c (cell2), s=1 keeps a1c (cell1) ----
        u64 keep[8];
#pragma unroll
        for (int i = 0; i < 8; ++i) {
            u64 sv = s ? a2c[i] : a1c[i];
            u64 rv = __shfl_xor_sync(0xFFFFFFFFu, sv, 16);
            keep[i] = add2(s ? a1c[i] : a2c[i], rv);
        }

        // ---- split update: s=0 -> h2(t), s=1 -> h1(t+1) ----
        float* hw = s ? h1n : h2c;
        gates_update(keep, a0, d0, bit0, bit1, cst, hw, rowj, jv);

        __syncthreads();
    }

    // final fc for t = 511
    if (tid < 128) {
        const float* h2o = buf + H2OFF + ((TT - 1) & 1) * HBUF;
        int b = tid >> 3, qq = tid & 7;
        float a = 0.f;
        for (int k = qq; k < HH; k += 8) {
            int rk = k + (k >= KQ);
            a += h2o[(rk << 4) + b] * buf[FCWOFF + k];
        }
        a += __shfl_xor_sync(0xFFFFFFFFu, a, 1);
        a += __shfl_xor_sync(0xFFFFFFFFu, a, 2);
        a += __shfl_xor_sync(0xFFFFFFFFu, a, 4);
        if (qq == 0) out[(size_t)(b0 + b) * TT + (TT - 1)] = a + fcb;
    }
}

extern "C" void kernel_launch(void* const* d_in, const int* in_sizes, int n_in,
                              void* d_out, int out_size)
{
    const float* x    = (const float*)d_in[0];
    // d_in[1] = future (0) — ignored
    const float* Wih1 = (const float*)d_in[2];
    const float* bih1 = (const float*)d_in[3];
    const float* Whh1 = (const float*)d_in[4];
    const float* bhh1 = (const float*)d_in[5];
    const float* Wih2 = (const float*)d_in[6];
    const float* bih2 = (const float*)d_in[7];
    const float* Whh2 = (const float*)d_in[8];
    const float* bhh2 = (const float*)d_in[9];
    const float* fcw  = (const float*)d_in[10];
    const float* fcb  = (const float*)d_in[11];
    float* out = (float*)d_out;

    lstm2_ksplit1b_kernel<<<BB / BT, NT>>>(
        x, Wih1, bih1, Whh1, bhh1, Wih2, bih2, Whh2, bhh2, fcw, fcb, out);
}

// round 16
// speedup vs baseline: 1.0802x; 1.0802x over previous
#include <cuda_runtime.h>
#include <cstddef>

#define HH 51
#define NT 224       // 7 warps: warp w owns units j = 8w..8w+7, lane = cls*8 + (j&7)
#define BT 16
#define TT 512
#define BB 2048
#define TCH 64

// dynamic smem layout (floats)
#define WSTRIDE 224
#define SW_F   (HH*WSTRIDE)       // 11424 per weight array
#define OFF_W1 0
#define OFF_WI (SW_F)
#define OFF_WH (2*SW_F)
#define OFF_H1 (3*SW_F)           // [2][832]
#define OFF_H2 (OFF_H1 + 2*832)
#define OFF_XS (OFF_H2 + 2*832)   // [64][16]
#define OFF_FC (OFF_XS + 1024)
#define SMF    (OFF_FC + 64)

typedef unsigned long long u64;

__device__ __forceinline__ u64 pack2(float lo, float hi) {
    u64 r; asm("mov.b64 %0, {%1,%2};" : "=l"(r) : "f"(lo), "f"(hi)); return r;
}
__device__ __forceinline__ void unpack2(u64 v, float& lo, float& hi) {
    asm("mov.b64 {%0,%1}, %2;" : "=f"(lo), "=f"(hi) : "l"(v));
}
__device__ __forceinline__ u64 fma2(u64 a, u64 b, u64 c) {
    u64 d; asm("fma.rn.f32x2 %0, %1, %2, %3;" : "=l"(d) : "l"(a), "l"(b), "l"(c)); return d;
}
// v PRE-SCALED by log2 const (weights folded). act = a*rcp(1+ex2(v)) + d
__device__ __forceinline__ float actf2(float v, float a, float d) {
    float e; asm("ex2.approx.ftz.f32 %0, %1;" : "=f"(e) : "f"(v));
    float r; asm("rcp.approx.ftz.f32 %0, %1;" : "=f"(r) : "f"(1.f + e));
    return fmaf(a, r, d);
}
#define C_SIG (-1.442695041f)
#define C_TNH ( 2.885390082f)
__device__ __forceinline__ float tanh_c(float v) {
    float e; asm("ex2.approx.ftz.f32 %0, %1;" : "=f"(e) : "f"(v * C_TNH));
    float r; asm("rcp.approx.ftz.f32 %0, %1;" : "=f"(r) : "f"(1.f + e));
    return fmaf(-2.f, r, 1.f);
}

// Transpose gate x batch inside the warp, update cell state (regs), write h row.
__device__ __forceinline__ void gates_update(
    u64 acc[8], float a0, float d0,
    int bit0, int bit1, float (&cst)[4],
    float* __restrict__ hw, int j, bool jv)
{
    float s[16];
#pragma unroll
    for (int i = 0; i < 8; ++i) unpack2(acc[i], s[2*i], s[2*i+1]);
#pragma unroll
    for (int i = 0; i < 16; ++i) s[i] = actf2(s[i], a0, d0);

    float a1[8];
    {
        const int qx0 = bit0 ? 0 : 1, qx1 = bit0 ? 2 : 3;
        const int qk0 = bit0 ? 1 : 0, qk1 = bit0 ? 3 : 2;
        float ex[8];
#pragma unroll
        for (int i = 0; i < 4; ++i) { ex[i] = s[qx0*4+i]; ex[4+i] = s[qx1*4+i]; }
#pragma unroll
        for (int i = 0; i < 8; ++i) a1[i] = __shfl_xor_sync(0xFFFFFFFFu, ex[i], 8);
        float k0[8];
#pragma unroll
        for (int i = 0; i < 4; ++i) { k0[i] = s[qk0*4+i]; k0[4+i] = s[qk1*4+i]; }
#pragma unroll
        for (int i = 0; i < 8; ++i) s[i] = k0[i];
    }
    float r0[4], r1[4];
    {
        float ex[8];
#pragma unroll
        for (int i = 0; i < 4; ++i) {
            ex[i]   = bit1 ? s[i]  : s[4+i];
            ex[4+i] = bit1 ? a1[i] : a1[4+i];
        }
#pragma unroll
        for (int i = 0; i < 8; ++i) ex[i] = __shfl_xor_sync(0xFFFFFFFFu, ex[i], 16);
#pragma unroll
        for (int i = 0; i < 4; ++i) {
            r0[i] = ex[i]; r1[i] = ex[4+i];
            s[i]  = bit1 ? s[4+i]  : s[i];
            a1[i] = bit1 ? a1[4+i] : a1[i];
        }
    }
    float4 hv;
    float* hp = &hv.x;
#pragma unroll
    for (int i = 0; i < 4; ++i) {
        float iv = bit1 ? (bit0 ? r1[i] : r0[i]) : (bit0 ? a1[i] : s[i]);
        float fv = bit1 ? (bit0 ? r0[i] : r1[i]) : (bit0 ? s[i]  : a1[i]);
        float gv = bit1 ? (bit0 ? a1[i] : s[i])  : (bit0 ? r1[i] : r0[i]);
        float ov = bit1 ? (bit0 ? s[i]  : a1[i]) : (bit0 ? r0[i] : r1[i]);
        float c = fv * cst[i] + iv * gv;
        cst[i] = c;
        hp[i] = ov * tanh_c(c);
    }
    if (jv) *(float4*)&hw[(j << 4) + (bit1*2 + bit0)*4] = hv;
}

__global__ void __launch_bounds__(NT, 1) lstm2_smw_kernel(
    const float* __restrict__ x,
    const float* __restrict__ Wih1, const float* __restrict__ bih1,
    const float* __restrict__ Whh1, const float* __restrict__ bhh1,
    const float* __restrict__ Wih2, const float* __restrict__ bih2,
    const float* __restrict__ Whh2, const float* __restrict__ bhh2,
    const float* __restrict__ fcwg, const float* __restrict__ fcbg,
    float* __restrict__ out)
{
    extern __shared__ __align__(16) float sm[];
    float* sW1  = sm + OFF_W1;    // [51][224] keyed by tid: sW1[k*224+tid] = sc*Whh1[gate(tid)][k]
    float* sWi  = sm + OFF_WI;
    float* sWh  = sm + OFF_WH;
    float* h1d  = sm + OFF_H1;    // [2][52*16] ping-pong
    float* h2d  = sm + OFF_H2;
    float* xs2  = sm + OFF_XS;    // [64][16]
    float* sfcw = sm + OFF_FC;

    const int tid  = threadIdx.x;
    const int b0   = blockIdx.x * BT;
    const int lane = tid & 31, warp = tid >> 5;
    const int cls  = lane >> 3;                      // 0:i 1:f 2:g 3:o
    const int j    = warp * 8 + (lane & 7);          // 0..55 (51..55 pad)
    const bool jv  = (j < HH);
    const int gs   = cls*HH + (jv ? j : HH - 1);
    const int bit0 = cls & 1, bit1 = (cls >> 1) & 1;

    const float sc = (cls == 2) ? C_TNH : C_SIG;
    const float a0 = (cls == 2) ? -2.f  : 1.f;
    const float d0 = (cls == 2) ?  1.f  : 0.f;

    // ---- weight prep into SMEM (pre-scaled), column = tid ----
    for (int k = 0; k < HH; ++k) {
        sW1[k*WSTRIDE + tid] = sc * Whh1[gs*HH + k];
        sWi[k*WSTRIDE + tid] = sc * Wih2[gs*HH + k];
        sWh[k*WSTRIDE + tid] = sc * Whh2[gs*HH + k];
    }
    const float b1 = sc * (bih1[gs] + bhh1[gs]);
    const float b2 = sc * (bih2[gs] + bhh2[gs]);
    const float w1x = sc * Wih1[gs];
    const u64 b1d  = pack2(b1, b1);
    const u64 b2d  = pack2(b2, b2);
    const u64 wi1d = pack2(w1x, w1x);

    for (int i = tid; i < 2*832; i += NT) { h1d[i] = 0.f; h2d[i] = 0.f; }
    if (tid < HH) sfcw[tid] = fcwg[tid];
    const float fcb = fcbg[0];

    float c1s[4] = {0.f, 0.f, 0.f, 0.f};
    float c2s[4] = {0.f, 0.f, 0.f, 0.f};

    // stage x chunk 0
    for (int i = tid; i < BT*TCH; i += NT) {
        int b = i >> 6, u = i & 63;
        xs2[(u << 4) + b] = x[(size_t)(b0 + b) * TT + u];
    }
    __syncthreads();

    // ---- prologue: cell1 at t=0 (h1(-1)=0) ----
    {
        u64 a1c[8];
        const ulonglong2* xr = (const ulonglong2*)&xs2[0];
        ulonglong2 x01 = xr[0], x23 = xr[1], x45 = xr[2], x67 = xr[3];
        a1c[0] = fma2(wi1d, x01.x, b1d);
        a1c[1] = fma2(wi1d, x01.y, b1d);
        a1c[2] = fma2(wi1d, x23.x, b1d);
        a1c[3] = fma2(wi1d, x23.y, b1d);
        a1c[4] = fma2(wi1d, x45.x, b1d);
        a1c[5] = fma2(wi1d, x45.y, b1d);
        a1c[6] = fma2(wi1d, x67.x, b1d);
        a1c[7] = fma2(wi1d, x67.y, b1d);
        gates_update(a1c, a0, d0, bit0, bit1, c1s, h1d, j, jv);
    }
    __syncthreads();

    // ================= main loop: ONE barrier per timestep =================
    for (int t = 0; t < TT; ++t) {
        // fc head for t-1
        if (t > 0 && tid < 128) {
            const float* h2p = h2d + ((t - 1) & 1) * 832;
            int b = tid >> 3, q = tid & 7;
            float a = 0.f;
            for (int k = q; k < HH; k += 8)
                a += h2p[(k << 4) + b] * sfcw[k];
            a += __shfl_xor_sync(0xFFFFFFFFu, a, 1);
            a += __shfl_xor_sync(0xFFFFFFFFu, a, 2);
            a += __shfl_xor_sync(0xFFFFFFFFu, a, 4);
            if (q == 0) out[(size_t)(b0 + b) * TT + (t - 1)] = a + fcb;
        }

        const int tn = t + 1;
        if ((tn & 63) == 0 && t < TT - 1) {
            __syncthreads();
            for (int i = tid; i < BT*TCH; i += NT) {
                int b = i >> 6, u = i & 63;
                xs2[(u << 4) + b] = x[(size_t)(b0 + b) * TT + tn + u];
            }
            __syncthreads();
        }
        const int tc = tn & 63;   // stale at t=511; discarded

        const float* h1cur = h1d + (t & 1) * 832;
        const float* h2prv = h2d + ((t + 1) & 1) * 832;
        float*       h1nxt = h1d + ((t + 1) & 1) * 832;
        float*       h2cur = h2d + (t & 1) * 832;

        u64 a1c[8], a2c[8];
        {
            const ulonglong2* xr = (const ulonglong2*)&xs2[tc << 4];
            ulonglong2 x01 = xr[0], x23 = xr[1], x45 = xr[2], x67 = xr[3];
            a1c[0] = fma2(wi1d, x01.x, b1d);
            a1c[1] = fma2(wi1d, x01.y, b1d);
            a1c[2] = fma2(wi1d, x23.x, b1d);
            a1c[3] = fma2(wi1d, x23.y, b1d);
            a1c[4] = fma2(wi1d, x45.x, b1d);
            a1c[5] = fma2(wi1d, x45.y, b1d);
            a1c[6] = fma2(wi1d, x67.x, b1d);
            a1c[7] = fma2(wi1d, x67.y, b1d);
        }
#pragma unroll
        for (int i = 0; i < 8; ++i) a2c[i] = b2d;

#pragma unroll
        for (int k = 0; k < HH; ++k) {
            float w1s = sW1[k*WSTRIDE + tid];
            float wis = sWi[k*WSTRIDE + tid];
            float whs = sWh[k*WSTRIDE + tid];
            u64 w1 = pack2(w1s, w1s);
            u64 wi = pack2(wis, wis);
            u64 wh = pack2(whs, whs);
            const ulonglong2* hp = (const ulonglong2*)&h1cur[k << 4];
            const ulonglong2* hq = (const ulonglong2*)&h2prv[k << 4];
            ulonglong2 p0 = hp[0], p1 = hp[1], p2 = hp[2], p3 = hp[3];
            ulonglong2 q0 = hq[0], q1 = hq[1], q2 = hq[2], q3 = hq[3];
            a1c[0] = fma2(w1, p0.x, a1c[0]);
            a1c[1] = fma2(w1, p0.y, a1c[1]);
            a1c[2] = fma2(w1, p1.x, a1c[2]);
            a1c[3] = fma2(w1, p1.y, a1c[3]);
            a1c[4] = fma2(w1, p2.x, a1c[4]);
            a1c[5] = fma2(w1, p2.y, a1c[5]);
            a1c[6] = fma2(w1, p3.x, a1c[6]);
            a1c[7] = fma2(w1, p3.y, a1c[7]);
            a2c[0] = fma2(wi, p0.x, a2c[0]);
            a2c[1] = fma2(wi, p0.y, a2c[1]);
            a2c[2] = fma2(wi, p1.x, a2c[2]);
            a2c[3] = fma2(wi, p1.y, a2c[3]);
            a2c[4] = fma2(wi, p2.x, a2c[4]);
            a2c[5] = fma2(wi, p2.y, a2c[5]);
            a2c[6] = fma2(wi, p3.x, a2c[6]);
            a2c[7] = fma2(wi, p3.y, a2c[7]);
            a2c[0] = fma2(wh, q0.x, a2c[0]);
            a2c[1] = fma2(wh, q0.y, a2c[1]);
            a2c[2] = fma2(wh, q1.x, a2c[2]);
            a2c[3] = fma2(wh, q1.y, a2c[3]);
            a2c[4] = fma2(wh, q2.x, a2c[4]);
            a2c[5] = fma2(wh, q2.y, a2c[5]);
            a2c[6] = fma2(wh, q3.x, a2c[6]);
            a2c[7] = fma2(wh, q3.y, a2c[7]);
        }

        gates_update(a2c, a0, d0, bit0, bit1, c2s, h2cur, j, jv);
        gates_update(a1c, a0, d0, bit0, bit1, c1s, h1nxt, j, jv);

        __syncthreads();
    }

    // final fc for t = 511
    if (tid < 128) {
        const float* h2p = h2d + ((TT - 1) & 1) * 832;
        int b = tid >> 3, q = tid & 7;
        float a = 0.f;
        for (int k = q; k < HH; k += 8)
            a += h2p[(k << 4) + b] * sfcw[k];
        a += __shfl_xor_sync(0xFFFFFFFFu, a, 1);
        a += __shfl_xor_sync(0xFFFFFFFFu, a, 2);
        a += __shfl_xor_sync(0xFFFFFFFFu, a, 4);
        if (q == 0) out[(size_t)(b0 + b) * TT + (TT - 1)] = a + fcb;
    }
}

extern "C" void kernel_launch(void* const* d_in, const int* in_sizes, int n_in,
                              void* d_out, int out_size)
{
    const float* x    = (const float*)d_in[0];
    // d_in[1] = future (0) — ignored
    const float* Wih1 = (const float*)d_in[2];
    const float* bih1 = (const float*)d_in[3];
    const float* Whh1 = (const float*)d_in[4];
    const float* bhh1 = (const float*)d_in[5];
    const float* Wih2 = (const float*)d_in[6];
    const float* bih2 = (const float*)d_in[7];
    const float* Whh2 = (const float*)d_in[8];
    const float* bhh2 = (const float*)d_in[9];
    const float* fcw  = (const float*)d_in[10];
    const float* fcb  = (const float*)d_in[11];
    float* out = (float*)d_out;

    const size_t smem = SMF * sizeof(float);   // ~151 KB
    cudaFuncSetAttribute(lstm2_smw_kernel,
                         cudaFuncAttributeMaxDynamicSharedMemorySize, (int)smem);

    lstm2_smw_kernel<<<BB / BT, NT, smem>>>(
        x, Wih1, bih1, Whh1, bhh1, Wih2, bih2, Whh2, bhh2, fcw, fcb, out);
}